// round 1
// baseline (speedup 1.0000x reference)
#include <cuda_runtime.h>
#include <cuda_bf16.h>
#include <math.h>

// Problem constants (fixed by the reference)
#define NNODES 20000
#define NEDGES 320000
#define HDIM   512

// ---------------- scratch (device globals; no runtime allocation) ----------------
__device__ float    d_s [NNODES * HDIM];   // GEMM output
__device__ float    d_hA[NNODES * HDIM];   // layer activation ping
__device__ float    d_hB[NNODES * HDIM];   // layer activation pong
__device__ int      d_counts[NNODES];
__device__ int      d_rowptr[NNODES + 1];
__device__ int      d_rowoff[NNODES];
__device__ int      d_ecol[NEDGES];
__device__ float    d_eval[NEDGES];
__device__ float    d_g[1024];             // accumulated [max | mean] over 3 layers
__device__ unsigned d_gmax[HDIM];
__device__ float    d_gsum[HDIM];

// ---------------- init: zero counters / accumulators ----------------
__global__ void init_kernel() {
    int i = blockIdx.x * blockDim.x + threadIdx.x;
    if (i < NNODES) d_counts[i] = 0;
    if (i < 1024)   d_g[i] = 0.0f;
    if (i < HDIM) { d_gmax[i] = 0u; d_gsum[i] = 0.0f; }
}

// ---------------- CSR build ----------------
__global__ void hist_kernel(const int* __restrict__ rows) {
    int e = blockIdx.x * blockDim.x + threadIdx.x;
    if (e < NEDGES) atomicAdd(&d_counts[rows[e]], 1);
}

// single-block inclusive scan over 20000 counts -> rowptr
__global__ void scan_kernel() {
    __shared__ int sums[1024];
    const int CH = 20;                      // 1024*20 = 20480 >= 20000
    int t = threadIdx.x;
    int base = t * CH;
    int local[CH];
    int run = 0;
#pragma unroll
    for (int i = 0; i < CH; i++) {
        int idx = base + i;
        int v = (idx < NNODES) ? d_counts[idx] : 0;
        run += v;
        local[i] = run;
    }
    sums[t] = run;
    __syncthreads();
    for (int off = 1; off < 1024; off <<= 1) {
        int v = 0;
        if (t >= off) v = sums[t - off];
        __syncthreads();
        if (t >= off) sums[t] += v;
        __syncthreads();
    }
    int offset = (t > 0) ? sums[t - 1] : 0;
#pragma unroll
    for (int i = 0; i < CH; i++) {
        int idx = base + i;
        if (idx < NNODES) d_rowptr[idx + 1] = offset + local[i];
    }
    if (t == 0) d_rowptr[0] = 0;
}

__global__ void copyoff_kernel() {
    int i = blockIdx.x * blockDim.x + threadIdx.x;
    if (i < NNODES) d_rowoff[i] = d_rowptr[i];
}

__global__ void scatter_kernel(const int* __restrict__ rows,
                               const int* __restrict__ cols,
                               const float* __restrict__ vals) {
    int e = blockIdx.x * blockDim.x + threadIdx.x;
    if (e < NEDGES) {
        int r = rows[e];
        int p = atomicAdd(&d_rowoff[r], 1);
        d_ecol[p] = cols[e];
        d_eval[p] = vals[e];
    }
}

// ---------------- SGEMM: C[M,512] = A[M,512] @ B[512,512], fp32 ----------------
// 128x128 blocktile, BK=8, 8x8 per thread, 256 threads.
#define BM 128
#define BN 128
#define BK 8
#define TM 8
#define TN 8

__global__ __launch_bounds__(256, 2)
void sgemm_kernel(const float* __restrict__ A, const float* __restrict__ B,
                  float* __restrict__ C, int M) {
    const int K = 512, Ncols = 512;
    __shared__ float As[BK][BM];   // transposed A tile
    __shared__ float Bs[BK][BN];

    int block_row = blockIdx.x * BM;
    int block_col = blockIdx.y * BN;
    int tid = threadIdx.x;

    // A tile load mapping: 128x8 floats = 256 float4; thread t -> row t/2, col (t%2)*4
    int a_r = tid >> 1;
    int a_c = (tid & 1) * 4;
    // B tile load mapping: 8x128 floats = 256 float4; thread t -> row t/32, col (t%32)*4
    int b_r = tid >> 5;
    int b_c = (tid & 31) * 4;

    int t_row = (tid >> 4) * TM;   // 0..120
    int t_col = (tid & 15) * TN;   // 0..120

    float acc[TM][TN];
#pragma unroll
    for (int i = 0; i < TM; i++)
#pragma unroll
        for (int j = 0; j < TN; j++) acc[i][j] = 0.0f;

    for (int k0 = 0; k0 < K; k0 += BK) {
        // load A (guarded on M)
        int gr = block_row + a_r;
        float4 av = make_float4(0.f, 0.f, 0.f, 0.f);
        if (gr < M) av = *(const float4*)(A + (size_t)gr * K + k0 + a_c);
        As[a_c + 0][a_r] = av.x;
        As[a_c + 1][a_r] = av.y;
        As[a_c + 2][a_r] = av.z;
        As[a_c + 3][a_r] = av.w;
        // load B (always in-bounds: K,N = 512)
        float4 bv = *(const float4*)(B + (size_t)(k0 + b_r) * Ncols + block_col + b_c);
        *(float4*)&Bs[b_r][b_c] = bv;
        __syncthreads();

#pragma unroll
        for (int k = 0; k < BK; k++) {
            float4 a0 = *(const float4*)&As[k][t_row];
            float4 a1 = *(const float4*)&As[k][t_row + 4];
            float4 b0 = *(const float4*)&Bs[k][t_col];
            float4 b1 = *(const float4*)&Bs[k][t_col + 4];
            float af[TM] = {a0.x, a0.y, a0.z, a0.w, a1.x, a1.y, a1.z, a1.w};
            float bf[TN] = {b0.x, b0.y, b0.z, b0.w, b1.x, b1.y, b1.z, b1.w};
#pragma unroll
            for (int i = 0; i < TM; i++)
#pragma unroll
                for (int j = 0; j < TN; j++)
                    acc[i][j] = fmaf(af[i], bf[j], acc[i][j]);
        }
        __syncthreads();
    }

#pragma unroll
    for (int i = 0; i < TM; i++) {
        int row = block_row + t_row + i;
        if (row < M) {
            float4 v0 = make_float4(acc[i][0], acc[i][1], acc[i][2], acc[i][3]);
            float4 v1 = make_float4(acc[i][4], acc[i][5], acc[i][6], acc[i][7]);
            *(float4*)(C + (size_t)row * Ncols + block_col + t_col)     = v0;
            *(float4*)(C + (size_t)row * Ncols + block_col + t_col + 4) = v1;
        }
    }
}

// ---------------- CSR SpMM + bias + ReLU ----------------
// one block per row, 128 threads, float4 per thread (512 features)
__global__ __launch_bounds__(128)
void spmm_relu_kernel(const float* __restrict__ bias, float* __restrict__ out) {
    int r = blockIdx.x;
    int t = threadIdx.x;                 // 0..127
    int beg = d_rowptr[r];
    int end = d_rowptr[r + 1];
    float4 acc = make_float4(0.f, 0.f, 0.f, 0.f);
    int j = beg;
    // unroll-by-2 to keep two gathers in flight
    for (; j + 1 < end; j += 2) {
        int   c0 = d_ecol[j],     c1 = d_ecol[j + 1];
        float v0 = d_eval[j],     v1 = d_eval[j + 1];
        float4 s0 = *(const float4*)(d_s + (size_t)c0 * HDIM + t * 4);
        float4 s1 = *(const float4*)(d_s + (size_t)c1 * HDIM + t * 4);
        acc.x = fmaf(v0, s0.x, acc.x); acc.y = fmaf(v0, s0.y, acc.y);
        acc.z = fmaf(v0, s0.z, acc.z); acc.w = fmaf(v0, s0.w, acc.w);
        acc.x = fmaf(v1, s1.x, acc.x); acc.y = fmaf(v1, s1.y, acc.y);
        acc.z = fmaf(v1, s1.z, acc.z); acc.w = fmaf(v1, s1.w, acc.w);
    }
    if (j < end) {
        int   c0 = d_ecol[j];
        float v0 = d_eval[j];
        float4 s0 = *(const float4*)(d_s + (size_t)c0 * HDIM + t * 4);
        acc.x = fmaf(v0, s0.x, acc.x); acc.y = fmaf(v0, s0.y, acc.y);
        acc.z = fmaf(v0, s0.z, acc.z); acc.w = fmaf(v0, s0.w, acc.w);
    }
    float4 b = *(const float4*)(bias + t * 4);
    acc.x = fmaxf(acc.x + b.x, 0.f);
    acc.y = fmaxf(acc.y + b.y, 0.f);
    acc.z = fmaxf(acc.z + b.z, 0.f);
    acc.w = fmaxf(acc.w + b.w, 0.f);
    *(float4*)(out + (size_t)r * HDIM + t * 4) = acc;
}

// ---------------- pooling: column max & sum (values >= 0 after ReLU) ----------------
__global__ __launch_bounds__(512)
void pool_kernel(const float* __restrict__ h) {
    int f = threadIdx.x;               // 512 features
    float mx = 0.0f, sm = 0.0f;
    for (int n = blockIdx.x; n < NNODES; n += gridDim.x) {
        float v = h[(size_t)n * HDIM + f];
        mx = fmaxf(mx, v);
        sm += v;
    }
    atomicMax(&d_gmax[f], __float_as_uint(mx));   // valid: all values >= 0
    atomicAdd(&d_gsum[f], sm);
}

__global__ void combine_kernel() {
    int f = threadIdx.x;               // 512
    d_g[f]        += __uint_as_float(d_gmax[f]);
    d_g[512 + f]  += d_gsum[f] * (1.0f / (float)NNODES);
    d_gmax[f] = 0u;
    d_gsum[f] = 0.0f;
}

// ---------------- MLP head + log_softmax (single block) ----------------
__global__ __launch_bounds__(128)
void head_kernel(const float* __restrict__ l1W, const float* __restrict__ l1b,
                 const float* __restrict__ l2W, const float* __restrict__ l2b,
                 const float* __restrict__ l3W, const float* __restrict__ l3b,
                 float* __restrict__ out) {
    __shared__ float y1[128];
    __shared__ float y2[64];
    __shared__ float y3[10];
    int t = threadIdx.x;

    // layer 1: [1,1024] @ [1024,128]
    {
        float acc = 0.0f;
        for (int i = 0; i < 1024; i++)
            acc = fmaf(d_g[i], l1W[i * 128 + t], acc);
        y1[t] = fmaxf(acc + l1b[t], 0.0f);
    }
    __syncthreads();
    // layer 2: [1,128] @ [128,64]
    if (t < 64) {
        float acc = 0.0f;
#pragma unroll 8
        for (int i = 0; i < 128; i++)
            acc = fmaf(y1[i], l2W[i * 64 + t], acc);
        y2[t] = fmaxf(acc + l2b[t], 0.0f);
    }
    __syncthreads();
    // layer 3: [1,64] @ [64,10]
    if (t < 10) {
        float acc = 0.0f;
#pragma unroll
        for (int i = 0; i < 64; i++)
            acc = fmaf(y2[i], l3W[i * 10 + t], acc);
        y3[t] = acc + l3b[t];
    }
    __syncthreads();
    if (t == 0) {
        float m = -1e30f;
#pragma unroll
        for (int j = 0; j < 10; j++) m = fmaxf(m, y3[j]);
        float s = 0.0f;
#pragma unroll
        for (int j = 0; j < 10; j++) s += expf(y3[j] - m);
        float lse = m + logf(s);
#pragma unroll
        for (int j = 0; j < 10; j++) out[j] = y3[j] - lse;
    }
}

// ---------------- launch ----------------
extern "C" void kernel_launch(void* const* d_in, const int* in_sizes, int n_in,
                              void* d_out, int out_size) {
    const float* x        = (const float*)d_in[0];
    const int*   rows     = (const int*)  d_in[1];
    const int*   cols     = (const int*)  d_in[2];
    const float* adj_vals = (const float*)d_in[3];
    const float* W1 = (const float*)d_in[4];
    const float* b1 = (const float*)d_in[5];
    const float* W2 = (const float*)d_in[6];
    const float* b2 = (const float*)d_in[7];
    const float* W3 = (const float*)d_in[8];
    const float* b3 = (const float*)d_in[9];
    const float* l1W = (const float*)d_in[10];
    const float* l1b = (const float*)d_in[11];
    const float* l2W = (const float*)d_in[12];
    const float* l2b = (const float*)d_in[13];
    const float* l3W = (const float*)d_in[14];
    const float* l3b = (const float*)d_in[15];
    float* out = (float*)d_out;

    float* s_g;  cudaGetSymbolAddress((void**)&s_g,  d_s);
    float* hA_g; cudaGetSymbolAddress((void**)&hA_g, d_hA);
    float* hB_g; cudaGetSymbolAddress((void**)&hB_g, d_hB);

    // init + CSR build
    init_kernel<<<(NNODES + 255) / 256, 256>>>();
    hist_kernel<<<(NEDGES + 255) / 256, 256>>>(rows);
    scan_kernel<<<1, 1024>>>();
    copyoff_kernel<<<(NNODES + 255) / 256, 256>>>();
    scatter_kernel<<<(NEDGES + 255) / 256, 256>>>(rows, cols, adj_vals);

    dim3 gemm_grid((NNODES + BM - 1) / BM, HDIM / BN);  // (157, 4)

    // layer 1
    sgemm_kernel<<<gemm_grid, 256>>>(x, W1, s_g, NNODES);
    spmm_relu_kernel<<<NNODES, 128>>>(b1, hA_g);
    pool_kernel<<<256, 512>>>(hA_g);
    combine_kernel<<<1, 512>>>();

    // layer 2
    sgemm_kernel<<<gemm_grid, 256>>>(hA_g, W2, s_g, NNODES);
    spmm_relu_kernel<<<NNODES, 128>>>(b2, hB_g);
    pool_kernel<<<256, 512>>>(hB_g);
    combine_kernel<<<1, 512>>>();

    // layer 3
    sgemm_kernel<<<gemm_grid, 256>>>(hB_g, W3, s_g, NNODES);
    spmm_relu_kernel<<<NNODES, 128>>>(b3, hA_g);
    pool_kernel<<<256, 512>>>(hA_g);
    combine_kernel<<<1, 512>>>();

    // head
    head_kernel<<<1, 128>>>(l1W, l1b, l2W, l2b, l3W, l3b, out);
}

// round 3
// speedup vs baseline: 1.6559x; 1.6559x over previous
#include <cuda_runtime.h>
#include <cuda_bf16.h>
#include <math.h>
#include <stdint.h>

// Problem constants (fixed by the reference)
#define NNODES 20000
#define NEDGES 320000
#define HDIM   512
#define NPAD   20096            // 157 * 128, padded row count for GEMM tiles

// ---------------- scratch (device globals; no runtime allocation) ----------------
__device__ float           d_s [NNODES * HDIM];   // GEMM output
__device__ float           d_hA[NNODES * HDIM];   // layer activation ping
__device__ float           d_hB[NNODES * HDIM];   // layer activation pong
__device__ __nv_bfloat16   d_Ah[NPAD * HDIM];     // activation hi (bf16), padded
__device__ __nv_bfloat16   d_Al[NPAD * HDIM];     // activation lo (bf16), padded
__device__ __nv_bfloat16   d_Wth[HDIM * HDIM];    // W^T hi (bf16), [N,K] layout
__device__ __nv_bfloat16   d_Wtl[HDIM * HDIM];    // W^T lo
__device__ int      d_counts[NNODES];
__device__ int      d_rowptr[NNODES + 1];
__device__ int      d_rowoff[NNODES];
__device__ int      d_ecol[NEDGES];
__device__ float    d_eval[NEDGES];
__device__ float    d_g[1024];             // accumulated [max | mean] over 3 layers
__device__ unsigned d_gmax[HDIM];
__device__ float    d_gsum[HDIM];

// ================= PTX helpers (generic compute_103-safe) =================
__device__ __forceinline__ uint32_t smem_u32(const void* p) {
    uint32_t a;
    asm("{ .reg .u64 t; cvta.to.shared.u64 t, %1; cvt.u32.u64 %0, t; }" : "=r"(a) : "l"(p));
    return a;
}
__device__ __forceinline__ void cp_async16(uint32_t dst, const void* src) {
    asm volatile("cp.async.cg.shared.global [%0], [%1], 16;" :: "r"(dst), "l"(src));
}
#define CP_COMMIT() asm volatile("cp.async.commit_group;" ::: "memory")
#define CP_WAIT1()  asm volatile("cp.async.wait_group 1;" ::: "memory")

__device__ __forceinline__ void ldsm_x4(uint32_t* r, uint32_t addr) {
    asm volatile("ldmatrix.sync.aligned.m8n8.x4.shared.b16 {%0,%1,%2,%3}, [%4];"
        : "=r"(r[0]), "=r"(r[1]), "=r"(r[2]), "=r"(r[3]) : "r"(addr));
}
__device__ __forceinline__ void mma_bf16(float* c, const uint32_t* a, const uint32_t* b) {
    asm volatile(
        "mma.sync.aligned.m16n8k16.row.col.f32.bf16.bf16.f32 "
        "{%0,%1,%2,%3}, {%4,%5,%6,%7}, {%8,%9}, {%0,%1,%2,%3};"
        : "+f"(c[0]), "+f"(c[1]), "+f"(c[2]), "+f"(c[3])
        : "r"(a[0]), "r"(a[1]), "r"(a[2]), "r"(a[3]), "r"(b[0]), "r"(b[1]));
}

// ---------------- init: zero counters / accumulators ----------------
__global__ void init_kernel() {
    int i = blockIdx.x * blockDim.x + threadIdx.x;
    if (i < NNODES) d_counts[i] = 0;
    if (i < 1024)   d_g[i] = 0.0f;
    if (i < HDIM) { d_gmax[i] = 0u; d_gsum[i] = 0.0f; }
}

// ---------------- CSR build ----------------
__global__ void hist_kernel(const int* __restrict__ rows) {
    int e = blockIdx.x * blockDim.x + threadIdx.x;
    if (e < NEDGES) atomicAdd(&d_counts[rows[e]], 1);
}

__global__ void scan_kernel() {
    __shared__ int sums[1024];
    const int CH = 20;
    int t = threadIdx.x;
    int base = t * CH;
    int local[CH];
    int run = 0;
#pragma unroll
    for (int i = 0; i < CH; i++) {
        int idx = base + i;
        int v = (idx < NNODES) ? d_counts[idx] : 0;
        run += v;
        local[i] = run;
    }
    sums[t] = run;
    __syncthreads();
    for (int off = 1; off < 1024; off <<= 1) {
        int v = 0;
        if (t >= off) v = sums[t - off];
        __syncthreads();
        if (t >= off) sums[t] += v;
        __syncthreads();
    }
    int offset = (t > 0) ? sums[t - 1] : 0;
#pragma unroll
    for (int i = 0; i < CH; i++) {
        int idx = base + i;
        if (idx < NNODES) d_rowptr[idx + 1] = offset + local[i];
    }
    if (t == 0) d_rowptr[0] = 0;
}

__global__ void copyoff_kernel() {
    int i = blockIdx.x * blockDim.x + threadIdx.x;
    if (i < NNODES) d_rowoff[i] = d_rowptr[i];
}

__global__ void scatter_kernel(const int* __restrict__ rows,
                               const int* __restrict__ cols,
                               const float* __restrict__ vals) {
    int e = blockIdx.x * blockDim.x + threadIdx.x;
    if (e < NEDGES) {
        int r = rows[e];
        int p = atomicAdd(&d_rowoff[r], 1);
        d_ecol[p] = cols[e];
        d_eval[p] = vals[e];
    }
}

// ---------------- fp32 -> bf16 hi/lo split (vectorized x4) ----------------
__global__ void convert_hilo_kernel(const float* __restrict__ src,
                                    __nv_bfloat16* __restrict__ hi,
                                    __nv_bfloat16* __restrict__ lo, int n4) {
    int i = blockIdx.x * blockDim.x + threadIdx.x;
    if (i >= n4) return;
    float4 v = ((const float4*)src)[i];
    __nv_bfloat16 h0 = __float2bfloat16(v.x);
    __nv_bfloat16 h1 = __float2bfloat16(v.y);
    __nv_bfloat16 h2 = __float2bfloat16(v.z);
    __nv_bfloat16 h3 = __float2bfloat16(v.w);
    __nv_bfloat16 l0 = __float2bfloat16(v.x - __bfloat162float(h0));
    __nv_bfloat16 l1 = __float2bfloat16(v.y - __bfloat162float(h1));
    __nv_bfloat16 l2 = __float2bfloat16(v.z - __bfloat162float(h2));
    __nv_bfloat16 l3 = __float2bfloat16(v.w - __bfloat162float(h3));
    ((__nv_bfloat162*)hi)[2 * i]     = __nv_bfloat162(h0, h1);
    ((__nv_bfloat162*)hi)[2 * i + 1] = __nv_bfloat162(h2, h3);
    ((__nv_bfloat162*)lo)[2 * i]     = __nv_bfloat162(l0, l1);
    ((__nv_bfloat162*)lo)[2 * i + 1] = __nv_bfloat162(l2, l3);
}

// ---------------- W [K,N] -> W^T [N,K] with hi/lo bf16 split ----------------
__global__ void transconv_kernel(const float* __restrict__ W,
                                 __nv_bfloat16* __restrict__ th,
                                 __nv_bfloat16* __restrict__ tl) {
    __shared__ float t[32][33];
    int bx = blockIdx.x * 32, by = blockIdx.y * 32;
    int x = threadIdx.x, y = threadIdx.y;   // 32 x 8
#pragma unroll
    for (int j = 0; j < 32; j += 8)
        t[y + j][x] = W[(size_t)(by + y + j) * HDIM + bx + x];
    __syncthreads();
#pragma unroll
    for (int j = 0; j < 32; j += 8) {
        float v = t[x][y + j];
        __nv_bfloat16 h = __float2bfloat16(v);
        __nv_bfloat16 l = __float2bfloat16(v - __bfloat162float(h));
        size_t o = (size_t)(bx + y + j) * HDIM + by + x;
        th[o] = h;
        tl[o] = l;
    }
}

// ---------------- HMMA bf16x3 GEMM: C[M,512] = A @ B^T ----------------
// A: hi/lo bf16 [NPAD,512] row-major. B: W^T hi/lo bf16 [512,512] ([N,K], K contiguous).
// Block tile 128x128, BK=64, double-buffered cp.async, 8 warps (2x4), warp tile 64x32.
#define TILE_B   16384                 // 128 rows x 64 bf16 x 2B (128B rows)
#define STAGE_B  (4 * TILE_B)          // Ah, Al, Bh, Bl
#define DYN_SMEM (2 * STAGE_B)         // 131072

// per-tile cp.async loader: 128 rows x 8 chunks(16B); thread -> (row=tid/2, 4 chunks)
__device__ __forceinline__ void load_tile(uint32_t smem_base,
                                          const __nv_bfloat16* __restrict__ src,
                                          int row_base, int k0, int tid) {
    int row = tid >> 1;
    int c0  = (tid & 1) * 4;
    const __nv_bfloat16* g = src + (size_t)(row_base + row) * HDIM + k0;
    uint32_t sb = smem_base + row * 128;
    int xr = row & 7;
#pragma unroll
    for (int c = c0; c < c0 + 4; ++c)
        cp_async16(sb + ((c ^ xr) << 4), g + c * 8);
}

__global__ __launch_bounds__(256, 1)
void gemm_bf16x3_kernel(const __nv_bfloat16* __restrict__ Ah, const __nv_bfloat16* __restrict__ Al,
                        const __nv_bfloat16* __restrict__ Bh, const __nv_bfloat16* __restrict__ Bl,
                        float* __restrict__ C, int M) {
    extern __shared__ __align__(1024) char dsm[];

    const int tid  = threadIdx.x;
    const int wid  = tid >> 5;
    const int lane = tid & 31;
    const int warp_m = wid >> 2;     // 0..1
    const int warp_n = wid & 3;      // 0..3
    const int block_row = blockIdx.x * 128;
    const int block_col = blockIdx.y * 128;

    uint32_t s_base = smem_u32(dsm);

    float acc[4][4][4];
#pragma unroll
    for (int i = 0; i < 4; i++)
#pragma unroll
        for (int j = 0; j < 4; j++)
#pragma unroll
            for (int q = 0; q < 4; q++) acc[i][j][q] = 0.0f;

    // prologue: stage 0 (k0=0), stage 1 (k0=64)
    {
        uint32_t st = s_base;
        load_tile(st,              Ah, block_row, 0, tid);
        load_tile(st + TILE_B,     Al, block_row, 0, tid);
        load_tile(st + 2 * TILE_B, Bh, block_col, 0, tid);
        load_tile(st + 3 * TILE_B, Bl, block_col, 0, tid);
        CP_COMMIT();
        st = s_base + STAGE_B;
        load_tile(st,              Ah, block_row, 64, tid);
        load_tile(st + TILE_B,     Al, block_row, 64, tid);
        load_tile(st + 2 * TILE_B, Bh, block_col, 64, tid);
        load_tile(st + 3 * TILE_B, Bl, block_col, 64, tid);
        CP_COMMIT();
    }

    // per-lane ldmatrix geometry (row&7 invariant under +16-row steps)
    const int a_row  = warp_m * 64 + (lane & 15);
    const int a_half = lane >> 4;
    const int a_x    = a_row & 7;
    const int b_row  = warp_n * 32 + (lane & 15);
    const int b_half = lane >> 4;
    const int b_x    = b_row & 7;

#pragma unroll 1
    for (int c = 0; c < 8; ++c) {
        CP_WAIT1();
        __syncthreads();
        uint32_t st  = s_base + (uint32_t)(c & 1) * STAGE_B;
        uint32_t sAh = st;
        uint32_t sAl = st + TILE_B;
        uint32_t sBh = st + 2 * TILE_B;
        uint32_t sBl = st + 3 * TILE_B;

#pragma unroll
        for (int kk = 0; kk < 4; ++kk) {
            uint32_t a_chunk_off = (uint32_t)(((2 * kk + a_half) ^ a_x) << 4);
            uint32_t b_chunk_off = (uint32_t)(((2 * kk + b_half) ^ b_x) << 4);
            uint32_t ah[4][4], al[4][4];
#pragma unroll
            for (int i = 0; i < 4; ++i) {
                uint32_t ro = (uint32_t)(a_row + i * 16) * 128 + a_chunk_off;
                ldsm_x4(ah[i], sAh + ro);
                ldsm_x4(al[i], sAl + ro);
            }
            uint32_t bh[4][2], bl[4][2];
#pragma unroll
            for (int p = 0; p < 2; ++p) {
                uint32_t ro = (uint32_t)(b_row + p * 16) * 128 + b_chunk_off;
                uint32_t r[4];
                ldsm_x4(r, sBh + ro);
                bh[2 * p][0] = r[0]; bh[2 * p][1] = r[2];
                bh[2 * p + 1][0] = r[1]; bh[2 * p + 1][1] = r[3];
                ldsm_x4(r, sBl + ro);
                bl[2 * p][0] = r[0]; bl[2 * p][1] = r[2];
                bl[2 * p + 1][0] = r[1]; bl[2 * p + 1][1] = r[3];
            }
#pragma unroll
            for (int i = 0; i < 4; ++i)
#pragma unroll
                for (int j = 0; j < 4; ++j) {
                    mma_bf16(acc[i][j], ah[i], bh[j]);
                    mma_bf16(acc[i][j], ah[i], bl[j]);
                    mma_bf16(acc[i][j], al[i], bh[j]);
                }
        }
        __syncthreads();
        if (c + 2 < 8) {
            uint32_t st2 = s_base + (uint32_t)(c & 1) * STAGE_B;
            int k0 = (c + 2) * 64;
            load_tile(st2,              Ah, block_row, k0, tid);
            load_tile(st2 + TILE_B,     Al, block_row, k0, tid);
            load_tile(st2 + 2 * TILE_B, Bh, block_col, k0, tid);
            load_tile(st2 + 3 * TILE_B, Bl, block_col, k0, tid);
        }
        CP_COMMIT();
    }

    // epilogue: direct fp32 stores (8B per quad-lane pair)
    const int r_in = lane >> 2;
    const int c_in = (lane & 3) * 2;
#pragma unroll
    for (int i = 0; i < 4; ++i) {
        int row0 = block_row + warp_m * 64 + i * 16 + r_in;
#pragma unroll
        for (int j = 0; j < 4; ++j) {
            int col = block_col + warp_n * 32 + j * 8 + c_in;
            if (row0 < M)
                *(float2*)(C + (size_t)row0 * HDIM + col) = make_float2(acc[i][j][0], acc[i][j][1]);
            if (row0 + 8 < M)
                *(float2*)(C + (size_t)(row0 + 8) * HDIM + col) = make_float2(acc[i][j][2], acc[i][j][3]);
        }
    }
}

// ---------------- CSR SpMM + bias + ReLU ----------------
__global__ __launch_bounds__(128)
void spmm_relu_kernel(const float* __restrict__ bias, float* __restrict__ out) {
    int r = blockIdx.x;
    int t = threadIdx.x;
    int beg = d_rowptr[r];
    int end = d_rowptr[r + 1];
    float4 acc = make_float4(0.f, 0.f, 0.f, 0.f);
    int j = beg;
    for (; j + 1 < end; j += 2) {
        int   c0 = d_ecol[j],     c1 = d_ecol[j + 1];
        float v0 = d_eval[j],     v1 = d_eval[j + 1];
        float4 s0 = *(const float4*)(d_s + (size_t)c0 * HDIM + t * 4);
        float4 s1 = *(const float4*)(d_s + (size_t)c1 * HDIM + t * 4);
        acc.x = fmaf(v0, s0.x, acc.x); acc.y = fmaf(v0, s0.y, acc.y);
        acc.z = fmaf(v0, s0.z, acc.z); acc.w = fmaf(v0, s0.w, acc.w);
        acc.x = fmaf(v1, s1.x, acc.x); acc.y = fmaf(v1, s1.y, acc.y);
        acc.z = fmaf(v1, s1.z, acc.z); acc.w = fmaf(v1, s1.w, acc.w);
    }
    if (j < end) {
        int   c0 = d_ecol[j];
        float v0 = d_eval[j];
        float4 s0 = *(const float4*)(d_s + (size_t)c0 * HDIM + t * 4);
        acc.x = fmaf(v0, s0.x, acc.x); acc.y = fmaf(v0, s0.y, acc.y);
        acc.z = fmaf(v0, s0.z, acc.z); acc.w = fmaf(v0, s0.w, acc.w);
    }
    float4 b = *(const float4*)(bias + t * 4);
    acc.x = fmaxf(acc.x + b.x, 0.f);
    acc.y = fmaxf(acc.y + b.y, 0.f);
    acc.z = fmaxf(acc.z + b.z, 0.f);
    acc.w = fmaxf(acc.w + b.w, 0.f);
    *(float4*)(out + (size_t)r * HDIM + t * 4) = acc;
}

// ---------------- pooling ----------------
__global__ __launch_bounds__(512)
void pool_kernel(const float* __restrict__ h) {
    int f = threadIdx.x;
    float mx = 0.0f, sm = 0.0f;
    for (int n = blockIdx.x; n < NNODES; n += gridDim.x) {
        float v = h[(size_t)n * HDIM + f];
        mx = fmaxf(mx, v);
        sm += v;
    }
    atomicMax(&d_gmax[f], __float_as_uint(mx));
    atomicAdd(&d_gsum[f], sm);
}

__global__ void combine_kernel() {
    int f = threadIdx.x;
    d_g[f]       += __uint_as_float(d_gmax[f]);
    d_g[512 + f] += d_gsum[f] * (1.0f / (float)NNODES);
    d_gmax[f] = 0u;
    d_gsum[f] = 0.0f;
}

// ---------------- MLP head + log_softmax ----------------
__global__ __launch_bounds__(128)
void head_kernel(const float* __restrict__ l1W, const float* __restrict__ l1b,
                 const float* __restrict__ l2W, const float* __restrict__ l2b,
                 const float* __restrict__ l3W, const float* __restrict__ l3b,
                 float* __restrict__ out) {
    __shared__ float y1[128];
    __shared__ float y2[64];
    __shared__ float y3[10];
    int t = threadIdx.x;
    {
        float acc = 0.0f;
        for (int i = 0; i < 1024; i++)
            acc = fmaf(d_g[i], l1W[i * 128 + t], acc);
        y1[t] = fmaxf(acc + l1b[t], 0.0f);
    }
    __syncthreads();
    if (t < 64) {
        float acc = 0.0f;
#pragma unroll 8
        for (int i = 0; i < 128; i++)
            acc = fmaf(y1[i], l2W[i * 64 + t], acc);
        y2[t] = fmaxf(acc + l2b[t], 0.0f);
    }
    __syncthreads();
    if (t < 10) {
        float acc = 0.0f;
#pragma unroll
        for (int i = 0; i < 64; i++)
            acc = fmaf(y2[i], l3W[i * 10 + t], acc);
        y3[t] = acc + l3b[t];
    }
    __syncthreads();
    if (t == 0) {
        float m = -1e30f;
#pragma unroll
        for (int j = 0; j < 10; j++) m = fmaxf(m, y3[j]);
        float s = 0.0f;
#pragma unroll
        for (int j = 0; j < 10; j++) s += expf(y3[j] - m);
        float lse = m + logf(s);
#pragma unroll
        for (int j = 0; j < 10; j++) out[j] = y3[j] - lse;
    }
}

// ---------------- launch ----------------
extern "C" void kernel_launch(void* const* d_in, const int* in_sizes, int n_in,
                              void* d_out, int out_size) {
    const float* x        = (const float*)d_in[0];
    const int*   rows     = (const int*)  d_in[1];
    const int*   cols     = (const int*)  d_in[2];
    const float* adj_vals = (const float*)d_in[3];
    const float* W1 = (const float*)d_in[4];
    const float* b1 = (const float*)d_in[5];
    const float* W2 = (const float*)d_in[6];
    const float* b2 = (const float*)d_in[7];
    const float* W3 = (const float*)d_in[8];
    const float* b3 = (const float*)d_in[9];
    const float* l1W = (const float*)d_in[10];
    const float* l1b = (const float*)d_in[11];
    const float* l2W = (const float*)d_in[12];
    const float* l2b = (const float*)d_in[13];
    const float* l3W = (const float*)d_in[14];
    const float* l3b = (const float*)d_in[15];
    float* out = (float*)d_out;

    float* s_g;  cudaGetSymbolAddress((void**)&s_g,  d_s);
    float* hA_g; cudaGetSymbolAddress((void**)&hA_g, d_hA);
    float* hB_g; cudaGetSymbolAddress((void**)&hB_g, d_hB);
    __nv_bfloat16 *Ah_g, *Al_g, *Wth_g, *Wtl_g;
    cudaGetSymbolAddress((void**)&Ah_g,  d_Ah);
    cudaGetSymbolAddress((void**)&Al_g,  d_Al);
    cudaGetSymbolAddress((void**)&Wth_g, d_Wth);
    cudaGetSymbolAddress((void**)&Wtl_g, d_Wtl);

    static bool attr_set = false;
    if (!attr_set) {
        cudaFuncSetAttribute(gemm_bf16x3_kernel,
                             cudaFuncAttributeMaxDynamicSharedMemorySize, DYN_SMEM);
        attr_set = true;
    }

    // init + CSR build
    init_kernel<<<(NNODES + 255) / 256, 256>>>();
    hist_kernel<<<(NEDGES + 255) / 256, 256>>>(rows);
    scan_kernel<<<1, 1024>>>();
    copyoff_kernel<<<(NNODES + 255) / 256, 256>>>();
    scatter_kernel<<<(NEDGES + 255) / 256, 256>>>(rows, cols, adj_vals);

    dim3 gemm_grid((NNODES + 127) / 128, HDIM / 128);   // (157, 4)
    dim3 tc_grid(16, 16), tc_blk(32, 8);
    const int n4 = NNODES * HDIM / 4;
    const int conv_blocks = (n4 + 255) / 256;

    // layer 1
    convert_hilo_kernel<<<conv_blocks, 256>>>(x, Ah_g, Al_g, n4);
    transconv_kernel<<<tc_grid, tc_blk>>>(W1, Wth_g, Wtl_g);
    gemm_bf16x3_kernel<<<gemm_grid, 256, DYN_SMEM>>>(Ah_g, Al_g, Wth_g, Wtl_g, s_g, NNODES);
    spmm_relu_kernel<<<NNODES, 128>>>(b1, hA_g);
    pool_kernel<<<256, 512>>>(hA_g);
    combine_kernel<<<1, 512>>>();

    // layer 2
    convert_hilo_kernel<<<conv_blocks, 256>>>(hA_g, Ah_g, Al_g, n4);
    transconv_kernel<<<tc_grid, tc_blk>>>(W2, Wth_g, Wtl_g);
    gemm_bf16x3_kernel<<<gemm_grid, 256, DYN_SMEM>>>(Ah_g, Al_g, Wth_g, Wtl_g, s_g, NNODES);
    spmm_relu_kernel<<<NNODES, 128>>>(b2, hB_g);
    pool_kernel<<<256, 512>>>(hB_g);
    combine_kernel<<<1, 512>>>();

    // layer 3
    convert_hilo_kernel<<<conv_blocks, 256>>>(hB_g, Ah_g, Al_g, n4);
    transconv_kernel<<<tc_grid, tc_blk>>>(W3, Wth_g, Wtl_g);
    gemm_bf16x3_kernel<<<gemm_grid, 256, DYN_SMEM>>>(Ah_g, Al_g, Wth_g, Wtl_g, s_g, NNODES);
    spmm_relu_kernel<<<NNODES, 128>>>(b3, hA_g);
    pool_kernel<<<256, 512>>>(hA_g);
    combine_kernel<<<1, 512>>>();

    // head
    head_kernel<<<1, 128>>>(l1W, l1b, l2W, l2b, l3W, l3b, out);
}